// round 1
// baseline (speedup 1.0000x reference)
#include <cuda_runtime.h>
#include <math.h>

#define MDIM 8192      // B*S rows
#define DDIM 1024      // d_model
#define SEQ  2048
#define BATCH 4
#define NH   16
#define DK   64

// Scratch (device globals — no allocation allowed)
__device__ float g_q[(size_t)MDIM * DDIM];
__device__ float g_k[(size_t)MDIM * DDIM];
__device__ float g_v[(size_t)MDIM * DDIM];
__device__ float g_attn[(size_t)MDIM * DDIM];

// ---------------------------------------------------------------------------
// SGEMM: C[m,n] = sum_k A[m,k] * W[n,k] + bias[n] (+ resid[m,n])
// A: M x K row-major, W: N x K row-major (torch Linear weight layout)
// 128x128 tile, BK=8, 256 threads, 8x8 per thread.
// Assumes M%128==0, N%128==0, K%8==0 (true here).
// ---------------------------------------------------------------------------
#define BM 128
#define BN 128
#define BK 8

__global__ __launch_bounds__(256) void sgemm_bt(
    const float* __restrict__ A, const float* __restrict__ W,
    const float* __restrict__ bias, const float* __restrict__ resid,
    float* __restrict__ C, int M, int N, int K)
{
    __shared__ __align__(16) float As[BK][BM];
    __shared__ __align__(16) float Bs[BK][BN];

    const int tid = threadIdx.x;
    const int tr = tid >> 4;          // 0..15
    const int tc = tid & 15;          // 0..15
    const int lr = tid >> 1;          // 0..127 (tile row for loads)
    const int lc = (tid & 1) << 2;    // 0 or 4 (k offset for loads)

    const float* Ag = A + (size_t)blockIdx.y * BM * K + (size_t)lr * K + lc;
    const float* Wg = W + (size_t)blockIdx.x * BN * K + (size_t)lr * K + lc;

    float acc[8][8];
#pragma unroll
    for (int i = 0; i < 8; i++)
#pragma unroll
        for (int j = 0; j < 8; j++) acc[i][j] = 0.f;

    for (int k0 = 0; k0 < K; k0 += BK) {
        float4 a4 = *(const float4*)(Ag + k0);
        float4 b4 = *(const float4*)(Wg + k0);
        As[lc + 0][lr] = a4.x; As[lc + 1][lr] = a4.y;
        As[lc + 2][lr] = a4.z; As[lc + 3][lr] = a4.w;
        Bs[lc + 0][lr] = b4.x; Bs[lc + 1][lr] = b4.y;
        Bs[lc + 2][lr] = b4.z; Bs[lc + 3][lr] = b4.w;
        __syncthreads();
#pragma unroll
        for (int kk = 0; kk < BK; kk++) {
            float ra[8], rb[8];
            *(float4*)&ra[0] = *(const float4*)&As[kk][tr * 8];
            *(float4*)&ra[4] = *(const float4*)&As[kk][tr * 8 + 4];
            *(float4*)&rb[0] = *(const float4*)&Bs[kk][tc * 8];
            *(float4*)&rb[4] = *(const float4*)&Bs[kk][tc * 8 + 4];
#pragma unroll
            for (int i = 0; i < 8; i++)
#pragma unroll
                for (int j = 0; j < 8; j++)
                    acc[i][j] = fmaf(ra[i], rb[j], acc[i][j]);
        }
        __syncthreads();
    }

    const int n0 = blockIdx.x * BN + tc * 8;
    float bv[8];
#pragma unroll
    for (int j = 0; j < 8; j++) bv[j] = bias[n0 + j];

#pragma unroll
    for (int i = 0; i < 8; i++) {
        const size_t m = (size_t)blockIdx.y * BM + tr * 8 + i;
        float* Crow = C + m * N + n0;
        float outv[8];
#pragma unroll
        for (int j = 0; j < 8; j++) outv[j] = acc[i][j] + bv[j];
        if (resid) {
            const float* Rrow = resid + m * N + n0;
#pragma unroll
            for (int j = 0; j < 8; j++) outv[j] += Rrow[j];
        }
        *(float4*)&Crow[0] = *(float4*)&outv[0];
        *(float4*)&Crow[4] = *(float4*)&outv[4];
    }
}

// ---------------------------------------------------------------------------
// Flash attention (fp32, online softmax).
// Grid: (SEQ/BR, BATCH*NH). 256 threads.
// Br=128 queries, Bc=64 keys per tile, d_k=64.
// Smem: Qs[128][65] + Ks[64][65] + Vs[64][65] + Ss[128][65] + 3*128 floats.
// ---------------------------------------------------------------------------
#define BR 128
#define BC 64
#define SPAD 65

__global__ __launch_bounds__(256) void flash_kernel(
    const float* __restrict__ Q, const float* __restrict__ Kg,
    const float* __restrict__ Vg, float* __restrict__ O)
{
    extern __shared__ float sm[];
    float* Qs  = sm;                       // BR*SPAD
    float* Ks  = Qs + BR * SPAD;           // BC*SPAD
    float* Vs  = Ks + BC * SPAD;           // BC*SPAD
    float* Ss  = Vs + BC * SPAD;           // BR*SPAD
    float* m_s = Ss + BR * SPAD;           // BR
    float* l_s = m_s + BR;                 // BR
    float* cr  = l_s + BR;                 // BR

    const int tid = threadIdx.x;
    const int tr2 = tid >> 4;              // 0..15  (8 q-rows each)
    const int tc2 = tid & 15;              // 0..15  (4 cols each)

    const int qb = blockIdx.x;             // query block
    const int bh = blockIdx.y;             // b*NH + h
    const int b  = bh >> 4;
    const int h  = bh & 15;
    const size_t base = (size_t)b * SEQ * DDIM + (size_t)h * DK;

    const float qscale = 1.0f / 32.0f;     // 1/sqrt(d_model)

    // Load Q block (scaled): 128x64
    {
        const float* Qg = Q + base + (size_t)(qb * BR) * DDIM;
        for (int t = tid; t < BR * DK / 4; t += 256) {
            int row = t >> 4;          // /16 float4 per row
            int c4  = (t & 15) << 2;
            float4 v = *(const float4*)(Qg + (size_t)row * DDIM + c4);
            Qs[row * SPAD + c4 + 0] = v.x * qscale;
            Qs[row * SPAD + c4 + 1] = v.y * qscale;
            Qs[row * SPAD + c4 + 2] = v.z * qscale;
            Qs[row * SPAD + c4 + 3] = v.w * qscale;
        }
    }
    if (tid < BR) { m_s[tid] = -1e30f; l_s[tid] = 0.f; }

    float o[8][4];
#pragma unroll
    for (int i = 0; i < 8; i++)
#pragma unroll
        for (int j = 0; j < 4; j++) o[i][j] = 0.f;

    for (int jt = 0; jt < SEQ / BC; jt++) {
        // Load K and V tiles (64x64)
        const float* Kt = Kg + base + (size_t)(jt * BC) * DDIM;
        const float* Vt = Vg + base + (size_t)(jt * BC) * DDIM;
        for (int t = tid; t < BC * DK / 4; t += 256) {
            int row = t >> 4;
            int c4  = (t & 15) << 2;
            float4 kv = *(const float4*)(Kt + (size_t)row * DDIM + c4);
            Ks[row * SPAD + c4 + 0] = kv.x;
            Ks[row * SPAD + c4 + 1] = kv.y;
            Ks[row * SPAD + c4 + 2] = kv.z;
            Ks[row * SPAD + c4 + 3] = kv.w;
            float4 vv = *(const float4*)(Vt + (size_t)row * DDIM + c4);
            Vs[row * SPAD + c4 + 0] = vv.x;
            Vs[row * SPAD + c4 + 1] = vv.y;
            Vs[row * SPAD + c4 + 2] = vv.z;
            Vs[row * SPAD + c4 + 3] = vv.w;
        }
        __syncthreads();

        // S = Qs @ Ks^T : each thread 8(q) x 4(key)
        {
            float s[8][4];
#pragma unroll
            for (int i = 0; i < 8; i++)
#pragma unroll
                for (int j = 0; j < 4; j++) s[i][j] = 0.f;
#pragma unroll 4
            for (int d = 0; d < DK; d++) {
                float qv[8], kv[4];
#pragma unroll
                for (int i = 0; i < 8; i++) qv[i] = Qs[(tr2 * 8 + i) * SPAD + d];
#pragma unroll
                for (int j = 0; j < 4; j++) kv[j] = Ks[(tc2 * 4 + j) * SPAD + d];
#pragma unroll
                for (int i = 0; i < 8; i++)
#pragma unroll
                    for (int j = 0; j < 4; j++)
                        s[i][j] = fmaf(qv[i], kv[j], s[i][j]);
            }
#pragma unroll
            for (int i = 0; i < 8; i++)
#pragma unroll
                for (int j = 0; j < 4; j++)
                    Ss[(tr2 * 8 + i) * SPAD + tc2 * 4 + j] = s[i][j];
        }
        __syncthreads();

        // Online softmax per row (128 threads, one row each)
        if (tid < BR) {
            float* row = Ss + tid * SPAD;
            float m_old = m_s[tid];
            float mx = m_old;
#pragma unroll 8
            for (int c = 0; c < BC; c++) mx = fmaxf(mx, row[c]);
            float cf = __expf(m_old - mx);
            float sum = 0.f;
#pragma unroll 8
            for (int c = 0; c < BC; c++) {
                float p = __expf(row[c] - mx);
                row[c] = p;
                sum += p;
            }
            l_s[tid] = l_s[tid] * cf + sum;
            m_s[tid] = mx;
            cr[tid]  = cf;
        }
        __syncthreads();

        // O = O*cf + P @ V  : each thread 8(q) x 4(d)
#pragma unroll
        for (int i = 0; i < 8; i++) {
            float cf = cr[tr2 * 8 + i];
#pragma unroll
            for (int j = 0; j < 4; j++) o[i][j] *= cf;
        }
#pragma unroll 4
        for (int kk = 0; kk < BC; kk++) {
            float pv[8], vv[4];
#pragma unroll
            for (int i = 0; i < 8; i++) pv[i] = Ss[(tr2 * 8 + i) * SPAD + kk];
#pragma unroll
            for (int j = 0; j < 4; j++) vv[j] = Vs[kk * SPAD + tc2 * 4 + j];
#pragma unroll
            for (int i = 0; i < 8; i++)
#pragma unroll
                for (int j = 0; j < 4; j++)
                    o[i][j] = fmaf(pv[i], vv[j], o[i][j]);
        }
        __syncthreads();
    }

    // Write out: O[b, qb*BR+row, h*64 + col] = o / l
    float* Ob = O + base + (size_t)(qb * BR) * DDIM;
#pragma unroll
    for (int i = 0; i < 8; i++) {
        int row = tr2 * 8 + i;
        float inv = 1.0f / l_s[row];
        float4 v;
        v.x = o[i][0] * inv; v.y = o[i][1] * inv;
        v.z = o[i][2] * inv; v.w = o[i][3] * inv;
        *(float4*)(Ob + (size_t)row * DDIM + tc2 * 4) = v;
    }
}

// ---------------------------------------------------------------------------
// LayerNorm: one block per row of 1024. 256 threads x 4 elems.
// ---------------------------------------------------------------------------
__global__ __launch_bounds__(256) void ln_kernel(
    const float* __restrict__ X, const float* __restrict__ gamma,
    const float* __restrict__ beta, float* __restrict__ out)
{
    const int row = blockIdx.x;
    const int c = threadIdx.x * 4;
    const float* x = X + (size_t)row * DDIM;

    float4 v = *(const float4*)(x + c);
    float s  = v.x + v.y + v.z + v.w;
    float ss = v.x * v.x + v.y * v.y + v.z * v.z + v.w * v.w;

    __shared__ float reds[32], redss[32];
    // warp reduce
    for (int off = 16; off > 0; off >>= 1) {
        s  += __shfl_xor_sync(0xffffffff, s, off);
        ss += __shfl_xor_sync(0xffffffff, ss, off);
    }
    const int wid = threadIdx.x >> 5, lid = threadIdx.x & 31;
    if (lid == 0) { reds[wid] = s; redss[wid] = ss; }
    __syncthreads();
    if (wid == 0) {
        float s2  = (lid < 8) ? reds[lid]  : 0.f;
        float ss2 = (lid < 8) ? redss[lid] : 0.f;
        for (int off = 4; off > 0; off >>= 1) {
            s2  += __shfl_xor_sync(0xffffffff, s2, off);
            ss2 += __shfl_xor_sync(0xffffffff, ss2, off);
        }
        if (lid == 0) { reds[0] = s2; redss[0] = ss2; }
    }
    __syncthreads();
    const float mu  = reds[0] * (1.0f / DDIM);
    const float var = redss[0] * (1.0f / DDIM) - mu * mu;
    const float rstd = rsqrtf(var + 1e-5f);

    float4 g  = *(const float4*)(gamma + c);
    float4 be = *(const float4*)(beta + c);
    float4 r;
    r.x = (v.x - mu) * rstd * g.x + be.x;
    r.y = (v.y - mu) * rstd * g.y + be.y;
    r.z = (v.z - mu) * rstd * g.z + be.z;
    r.w = (v.w - mu) * rstd * g.w + be.w;
    *(float4*)(out + (size_t)row * DDIM + c) = r;
}

// ---------------------------------------------------------------------------
extern "C" void kernel_launch(void* const* d_in, const int* in_sizes, int n_in,
                              void* d_out, int out_size)
{
    const float* q     = (const float*)d_in[0];
    const float* k     = (const float*)d_in[1];
    const float* v     = (const float*)d_in[2];
    const float* Wq    = (const float*)d_in[3];
    const float* bq    = (const float*)d_in[4];
    const float* Wk    = (const float*)d_in[5];
    const float* bk    = (const float*)d_in[6];
    const float* Wv    = (const float*)d_in[7];
    const float* bv    = (const float*)d_in[8];
    const float* Wo    = (const float*)d_in[9];
    const float* bo    = (const float*)d_in[10];
    const float* gamma = (const float*)d_in[11];
    const float* beta  = (const float*)d_in[12];
    float* out = (float*)d_out;

    float *pq, *pk, *pv, *pa;
    cudaGetSymbolAddress((void**)&pq, g_q);
    cudaGetSymbolAddress((void**)&pk, g_k);
    cudaGetSymbolAddress((void**)&pv, g_v);
    cudaGetSymbolAddress((void**)&pa, g_attn);

    const int FLASH_SMEM = (BR * SPAD * 2 + BC * SPAD * 2 + 3 * BR) * 4;
    cudaFuncSetAttribute((const void*)flash_kernel,
                         cudaFuncAttributeMaxDynamicSharedMemorySize, FLASH_SMEM);

    dim3 gg(DDIM / BN, MDIM / BM);  // (8, 64)
    sgemm_bt<<<gg, 256>>>(q, Wq, bq, nullptr, pq, MDIM, DDIM, DDIM);
    sgemm_bt<<<gg, 256>>>(k, Wk, bk, nullptr, pk, MDIM, DDIM, DDIM);
    sgemm_bt<<<gg, 256>>>(v, Wv, bv, nullptr, pv, MDIM, DDIM, DDIM);

    flash_kernel<<<dim3(SEQ / BR, BATCH * NH), 256, FLASH_SMEM>>>(pq, pk, pv, pa);

    // output projection + bias + residual, into g_k (free now)
    sgemm_bt<<<gg, 256>>>(pa, Wo, bo, q, pk, MDIM, DDIM, DDIM);

    ln_kernel<<<MDIM, 256>>>(pk, gamma, beta, out);
}

// round 2
// speedup vs baseline: 2.4749x; 2.4749x over previous
#include <cuda_runtime.h>
#include <math.h>

#define MDIM 8192      // B*S rows
#define DDIM 1024      // d_model
#define SEQ  2048
#define BATCH 4
#define NH   16
#define DK   64

// Scratch (device globals — no allocation allowed)
__device__ float g_q[(size_t)MDIM * DDIM];
__device__ float g_k[(size_t)MDIM * DDIM];
__device__ float g_v[(size_t)MDIM * DDIM];
__device__ float g_attn[(size_t)MDIM * DDIM];

// ---------------------------------------------------------------------------
// helpers
// ---------------------------------------------------------------------------
__device__ __forceinline__ float to_tf32(float x) {
    unsigned u;
    asm("cvt.rna.tf32.f32 %0, %1;" : "=r"(u) : "f"(x));
    return __uint_as_float(u);
}
__device__ __forceinline__ unsigned fu(float x) { return __float_as_uint(x); }

__device__ __forceinline__ void mma8(float* c,
                                     unsigned a0, unsigned a1, unsigned a2, unsigned a3,
                                     unsigned b0, unsigned b1) {
    asm volatile(
        "mma.sync.aligned.m16n8k8.row.col.f32.tf32.tf32.f32 "
        "{%0,%1,%2,%3}, {%4,%5,%6,%7}, {%8,%9}, {%0,%1,%2,%3};"
        : "+f"(c[0]), "+f"(c[1]), "+f"(c[2]), "+f"(c[3])
        : "r"(a0), "r"(a1), "r"(a2), "r"(a3), "r"(b0), "r"(b1));
}

// ---------------------------------------------------------------------------
// TF32 tensor-core GEMM: C[m,n] = sum_k A[m,k]*W[n,k] + bias[n] (+ resid)
// A: MxK row-major, W: NxK row-major. 128x128x16 tile, 256 thr, warp 32x64.
// ---------------------------------------------------------------------------
#define BM 128
#define BN 128
#define BKT 16
#define GSTR 136   // k-major smem stride; 136%32==8 -> conflict-free frags

__global__ __launch_bounds__(256) void sgemm_tc(
    const float* __restrict__ A, const float* __restrict__ W,
    const float* __restrict__ bias, const float* __restrict__ resid,
    float* __restrict__ C, int M, int N, int K)
{
    __shared__ float As[BKT * GSTR];
    __shared__ float Bs[BKT * GSTR];

    const int tid  = threadIdx.x;
    const int lane = tid & 31, warp = tid >> 5;
    const int qr = lane >> 2, qc = lane & 3;
    const int wm = (warp >> 1) * 32;   // warp row offset
    const int wn = (warp & 1) * 64;    // warp col offset

    const int lrow = tid >> 2;         // 0..63
    const int lk   = (tid & 3) * 4;    // 0,4,8,12

    const float* Ag = A + (size_t)(blockIdx.y * BM + lrow) * K + lk;
    const float* Wg = W + (size_t)(blockIdx.x * BN + lrow) * K + lk;
    const size_t rowstep = (size_t)64 * K;

    float4 pa0 = *(const float4*)(Ag);
    float4 pa1 = *(const float4*)(Ag + rowstep);
    float4 pb0 = *(const float4*)(Wg);
    float4 pb1 = *(const float4*)(Wg + rowstep);

    float acc[2][8][4];
#pragma unroll
    for (int mi = 0; mi < 2; mi++)
#pragma unroll
        for (int ni = 0; ni < 8; ni++)
#pragma unroll
            for (int j = 0; j < 4; j++) acc[mi][ni][j] = 0.f;

    for (int k0 = 0; k0 < K; k0 += BKT) {
        As[(lk + 0) * GSTR + lrow] = to_tf32(pa0.x);
        As[(lk + 1) * GSTR + lrow] = to_tf32(pa0.y);
        As[(lk + 2) * GSTR + lrow] = to_tf32(pa0.z);
        As[(lk + 3) * GSTR + lrow] = to_tf32(pa0.w);
        As[(lk + 0) * GSTR + lrow + 64] = to_tf32(pa1.x);
        As[(lk + 1) * GSTR + lrow + 64] = to_tf32(pa1.y);
        As[(lk + 2) * GSTR + lrow + 64] = to_tf32(pa1.z);
        As[(lk + 3) * GSTR + lrow + 64] = to_tf32(pa1.w);
        Bs[(lk + 0) * GSTR + lrow] = to_tf32(pb0.x);
        Bs[(lk + 1) * GSTR + lrow] = to_tf32(pb0.y);
        Bs[(lk + 2) * GSTR + lrow] = to_tf32(pb0.z);
        Bs[(lk + 3) * GSTR + lrow] = to_tf32(pb0.w);
        Bs[(lk + 0) * GSTR + lrow + 64] = to_tf32(pb1.x);
        Bs[(lk + 1) * GSTR + lrow + 64] = to_tf32(pb1.y);
        Bs[(lk + 2) * GSTR + lrow + 64] = to_tf32(pb1.z);
        Bs[(lk + 3) * GSTR + lrow + 64] = to_tf32(pb1.w);
        __syncthreads();

        if (k0 + BKT < K) {
            pa0 = *(const float4*)(Ag + k0 + BKT);
            pa1 = *(const float4*)(Ag + rowstep + k0 + BKT);
            pb0 = *(const float4*)(Wg + k0 + BKT);
            pb1 = *(const float4*)(Wg + rowstep + k0 + BKT);
        }

#pragma unroll
        for (int kk = 0; kk < BKT; kk += 8) {
            unsigned bfr[8][2];
#pragma unroll
            for (int ni = 0; ni < 8; ni++) {
                bfr[ni][0] = fu(Bs[(kk + qc) * GSTR + wn + ni * 8 + qr]);
                bfr[ni][1] = fu(Bs[(kk + qc + 4) * GSTR + wn + ni * 8 + qr]);
            }
#pragma unroll
            for (int mi = 0; mi < 2; mi++) {
                const int r0 = wm + mi * 16 + qr;
                unsigned a0 = fu(As[(kk + qc) * GSTR + r0]);
                unsigned a1 = fu(As[(kk + qc) * GSTR + r0 + 8]);
                unsigned a2 = fu(As[(kk + qc + 4) * GSTR + r0]);
                unsigned a3 = fu(As[(kk + qc + 4) * GSTR + r0 + 8]);
#pragma unroll
                for (int ni = 0; ni < 8; ni++)
                    mma8(acc[mi][ni], a0, a1, a2, a3, bfr[ni][0], bfr[ni][1]);
            }
        }
        __syncthreads();
    }

    // epilogue
#pragma unroll
    for (int mi = 0; mi < 2; mi++) {
        const int row = blockIdx.y * BM + wm + mi * 16 + qr;
#pragma unroll
        for (int ni = 0; ni < 8; ni++) {
            const int col = blockIdx.x * BN + wn + ni * 8 + qc * 2;
            const float b0 = bias[col], b1 = bias[col + 1];
            float x0 = acc[mi][ni][0] + b0, x1 = acc[mi][ni][1] + b1;
            float y0 = acc[mi][ni][2] + b0, y1 = acc[mi][ni][3] + b1;
            if (resid) {
                const float* r0p = resid + (size_t)row * N + col;
                const float* r1p = resid + (size_t)(row + 8) * N + col;
                x0 += r0p[0]; x1 += r0p[1];
                y0 += r1p[0]; y1 += r1p[1];
            }
            float2 v0 = {x0, x1}, v1 = {y0, y1};
            *(float2*)(C + (size_t)row * N + col) = v0;
            *(float2*)(C + (size_t)(row + 8) * N + col) = v1;
        }
    }
}

// ---------------------------------------------------------------------------
// Flash attention with TF32 tensor-core MMAs.
// Grid (SEQ/BR, BATCH*NH), 256 threads. Br=128 q, Bc=64 kv, d_k=64.
// ---------------------------------------------------------------------------
#define BR 128
#define BC 64
#define QSTR 68   // row-varying frag accesses: 68%32==4 -> conflict-free
#define VSTR 72   // k-varying  frag accesses: 72%32==8 -> conflict-free

__global__ __launch_bounds__(256) void flash_tc(
    const float* __restrict__ Q, const float* __restrict__ Kg,
    const float* __restrict__ Vg, float* __restrict__ O)
{
    extern __shared__ float sm[];
    float* Qs  = sm;                        // BR*QSTR
    float* Ks  = Qs + BR * QSTR;            // BC*QSTR
    float* Vs  = Ks + BC * QSTR;            // BC*VSTR
    float* Ss  = Vs + BC * VSTR;            // BR*QSTR
    float* m_s = Ss + BR * QSTR;            // BR
    float* l_s = m_s + BR;                  // BR
    float* cr  = l_s + BR;                  // BR

    const int tid  = threadIdx.x;
    const int lane = tid & 31, warp = tid >> 5;
    const int qr = lane >> 2, qc = lane & 3;
    const int wm = (warp >> 1) * 32;   // warp q-row offset (4 warps)
    const int wn = (warp & 1) * 32;    // warp col offset (2 warps)

    const int qb = blockIdx.x;
    const int bh = blockIdx.y;
    const int b  = bh >> 4;
    const int h  = bh & 15;
    const size_t base = (size_t)b * SEQ * DDIM + (size_t)h * DK;
    const float qscale = 1.0f / 32.0f;      // 1/sqrt(d_model)

    // Load Q (scaled, tf32-rounded)
    {
        const float* Qg = Q + base + (size_t)(qb * BR) * DDIM;
        for (int t = tid; t < BR * DK / 4; t += 256) {
            int row = t >> 4, c4 = (t & 15) << 2;
            float4 v = *(const float4*)(Qg + (size_t)row * DDIM + c4);
            Qs[row * QSTR + c4 + 0] = to_tf32(v.x * qscale);
            Qs[row * QSTR + c4 + 1] = to_tf32(v.y * qscale);
            Qs[row * QSTR + c4 + 2] = to_tf32(v.z * qscale);
            Qs[row * QSTR + c4 + 3] = to_tf32(v.w * qscale);
        }
    }
    if (tid < BR) { m_s[tid] = -1e30f; l_s[tid] = 0.f; }

    float oacc[2][4][4];
#pragma unroll
    for (int mi = 0; mi < 2; mi++)
#pragma unroll
        for (int ni = 0; ni < 4; ni++)
#pragma unroll
            for (int j = 0; j < 4; j++) oacc[mi][ni][j] = 0.f;

    for (int jt = 0; jt < SEQ / BC; jt++) {
        // Load K, V tiles (tf32-rounded)
        const float* Kt = Kg + base + (size_t)(jt * BC) * DDIM;
        const float* Vt = Vg + base + (size_t)(jt * BC) * DDIM;
        for (int t = tid; t < BC * DK / 4; t += 256) {
            int row = t >> 4, c4 = (t & 15) << 2;
            float4 kv = *(const float4*)(Kt + (size_t)row * DDIM + c4);
            Ks[row * QSTR + c4 + 0] = to_tf32(kv.x);
            Ks[row * QSTR + c4 + 1] = to_tf32(kv.y);
            Ks[row * QSTR + c4 + 2] = to_tf32(kv.z);
            Ks[row * QSTR + c4 + 3] = to_tf32(kv.w);
            float4 vv = *(const float4*)(Vt + (size_t)row * DDIM + c4);
            Vs[row * VSTR + c4 + 0] = to_tf32(vv.x);
            Vs[row * VSTR + c4 + 1] = to_tf32(vv.y);
            Vs[row * VSTR + c4 + 2] = to_tf32(vv.z);
            Vs[row * VSTR + c4 + 3] = to_tf32(vv.w);
        }
        __syncthreads();

        // S = Qs @ Ks^T  (warp tile 32x32)
        float sacc[2][4][4];
#pragma unroll
        for (int mi = 0; mi < 2; mi++)
#pragma unroll
            for (int ni = 0; ni < 4; ni++)
#pragma unroll
                for (int j = 0; j < 4; j++) sacc[mi][ni][j] = 0.f;

#pragma unroll
        for (int kk = 0; kk < DK; kk += 8) {
            unsigned bfr[4][2];
#pragma unroll
            for (int ni = 0; ni < 4; ni++) {
                bfr[ni][0] = fu(Ks[(wn + ni * 8 + qr) * QSTR + kk + qc]);
                bfr[ni][1] = fu(Ks[(wn + ni * 8 + qr) * QSTR + kk + qc + 4]);
            }
#pragma unroll
            for (int mi = 0; mi < 2; mi++) {
                const int r0 = wm + mi * 16 + qr;
                unsigned a0 = fu(Qs[r0 * QSTR + kk + qc]);
                unsigned a1 = fu(Qs[(r0 + 8) * QSTR + kk + qc]);
                unsigned a2 = fu(Qs[r0 * QSTR + kk + qc + 4]);
                unsigned a3 = fu(Qs[(r0 + 8) * QSTR + kk + qc + 4]);
#pragma unroll
                for (int ni = 0; ni < 4; ni++)
                    mma8(sacc[mi][ni], a0, a1, a2, a3, bfr[ni][0], bfr[ni][1]);
            }
        }
        // spill S to smem
#pragma unroll
        for (int mi = 0; mi < 2; mi++) {
            const int r0 = wm + mi * 16 + qr;
#pragma unroll
            for (int ni = 0; ni < 4; ni++) {
                const int c = wn + ni * 8 + qc * 2;
                Ss[r0 * QSTR + c]       = sacc[mi][ni][0];
                Ss[r0 * QSTR + c + 1]   = sacc[mi][ni][1];
                Ss[(r0 + 8) * QSTR + c]     = sacc[mi][ni][2];
                Ss[(r0 + 8) * QSTR + c + 1] = sacc[mi][ni][3];
            }
        }
        __syncthreads();

        // online softmax: 2 threads per row
        {
            const int row = tid >> 1, half = (tid & 1) * 32;
            float* rp = Ss + row * QSTR + half;
            const float m_old = m_s[row];
            float mx = -1e30f;
#pragma unroll
            for (int c = 0; c < 32; c++) mx = fmaxf(mx, rp[c]);
            mx = fmaxf(mx, __shfl_xor_sync(0xffffffff, mx, 1));
            mx = fmaxf(mx, m_old);
            float sum = 0.f;
#pragma unroll
            for (int c = 0; c < 32; c++) {
                float p = __expf(rp[c] - mx);
                rp[c] = p;
                sum += p;
            }
            sum += __shfl_xor_sync(0xffffffff, sum, 1);
            if ((tid & 1) == 0) {
                float cf = __expf(m_old - mx);
                l_s[row] = l_s[row] * cf + sum;
                m_s[row] = mx;
                cr[row]  = cf;
            }
        }
        __syncthreads();

        // rescale O, then O += P @ V
#pragma unroll
        for (int mi = 0; mi < 2; mi++) {
            const float cf0 = cr[wm + mi * 16 + qr];
            const float cf1 = cr[wm + mi * 16 + qr + 8];
#pragma unroll
            for (int ni = 0; ni < 4; ni++) {
                oacc[mi][ni][0] *= cf0; oacc[mi][ni][1] *= cf0;
                oacc[mi][ni][2] *= cf1; oacc[mi][ni][3] *= cf1;
            }
        }
#pragma unroll
        for (int kk = 0; kk < BC; kk += 8) {
            unsigned bfr[4][2];
#pragma unroll
            for (int ni = 0; ni < 4; ni++) {
                bfr[ni][0] = fu(Vs[(kk + qc) * VSTR + wn + ni * 8 + qr]);
                bfr[ni][1] = fu(Vs[(kk + qc + 4) * VSTR + wn + ni * 8 + qr]);
            }
#pragma unroll
            for (int mi = 0; mi < 2; mi++) {
                const int r0 = wm + mi * 16 + qr;
                unsigned a0 = fu(Ss[r0 * QSTR + kk + qc]);
                unsigned a1 = fu(Ss[(r0 + 8) * QSTR + kk + qc]);
                unsigned a2 = fu(Ss[r0 * QSTR + kk + qc + 4]);
                unsigned a3 = fu(Ss[(r0 + 8) * QSTR + kk + qc + 4]);
#pragma unroll
                for (int ni = 0; ni < 4; ni++)
                    mma8(oacc[mi][ni], a0, a1, a2, a3, bfr[ni][0], bfr[ni][1]);
            }
        }
        __syncthreads();
    }

    // write out O / l
    float* Ob = O + base + (size_t)(qb * BR) * DDIM;
#pragma unroll
    for (int mi = 0; mi < 2; mi++) {
        const int r = wm + mi * 16 + qr;
        const float inv0 = 1.0f / l_s[r];
        const float inv1 = 1.0f / l_s[r + 8];
#pragma unroll
        for (int ni = 0; ni < 4; ni++) {
            const int c = wn + ni * 8 + qc * 2;
            float2 v0 = {oacc[mi][ni][0] * inv0, oacc[mi][ni][1] * inv0};
            float2 v1 = {oacc[mi][ni][2] * inv1, oacc[mi][ni][3] * inv1};
            *(float2*)(Ob + (size_t)r * DDIM + c) = v0;
            *(float2*)(Ob + (size_t)(r + 8) * DDIM + c) = v1;
        }
    }
}

// ---------------------------------------------------------------------------
// LayerNorm: one block per row of 1024. 256 threads x 4 elems.
// ---------------------------------------------------------------------------
__global__ __launch_bounds__(256) void ln_kernel(
    const float* __restrict__ X, const float* __restrict__ gamma,
    const float* __restrict__ beta, float* __restrict__ out)
{
    const int row = blockIdx.x;
    const int c = threadIdx.x * 4;
    const float* x = X + (size_t)row * DDIM;

    float4 v = *(const float4*)(x + c);
    float s  = v.x + v.y + v.z + v.w;
    float ss = v.x * v.x + v.y * v.y + v.z * v.z + v.w * v.w;

    __shared__ float reds[32], redss[32];
    for (int off = 16; off > 0; off >>= 1) {
        s  += __shfl_xor_sync(0xffffffff, s, off);
        ss += __shfl_xor_sync(0xffffffff, ss, off);
    }
    const int wid = threadIdx.x >> 5, lid = threadIdx.x & 31;
    if (lid == 0) { reds[wid] = s; redss[wid] = ss; }
    __syncthreads();
    if (wid == 0) {
        float s2  = (lid < 8) ? reds[lid]  : 0.f;
        float ss2 = (lid < 8) ? redss[lid] : 0.f;
        for (int off = 4; off > 0; off >>= 1) {
            s2  += __shfl_xor_sync(0xffffffff, s2, off);
            ss2 += __shfl_xor_sync(0xffffffff, ss2, off);
        }
        if (lid == 0) { reds[0] = s2; redss[0] = ss2; }
    }
    __syncthreads();
    const float mu  = reds[0] * (1.0f / DDIM);
    const float var = redss[0] * (1.0f / DDIM) - mu * mu;
    const float rstd = rsqrtf(var + 1e-5f);

    float4 g  = *(const float4*)(gamma + c);
    float4 be = *(const float4*)(beta + c);
    float4 r;
    r.x = (v.x - mu) * rstd * g.x + be.x;
    r.y = (v.y - mu) * rstd * g.y + be.y;
    r.z = (v.z - mu) * rstd * g.z + be.z;
    r.w = (v.w - mu) * rstd * g.w + be.w;
    *(float4*)(out + (size_t)row * DDIM + c) = r;
}

// ---------------------------------------------------------------------------
extern "C" void kernel_launch(void* const* d_in, const int* in_sizes, int n_in,
                              void* d_out, int out_size)
{
    const float* q     = (const float*)d_in[0];
    const float* k     = (const float*)d_in[1];
    const float* v     = (const float*)d_in[2];
    const float* Wq    = (const float*)d_in[3];
    const float* bq    = (const float*)d_in[4];
    const float* Wk    = (const float*)d_in[5];
    const float* bk    = (const float*)d_in[6];
    const float* Wv    = (const float*)d_in[7];
    const float* bv    = (const float*)d_in[8];
    const float* Wo    = (const float*)d_in[9];
    const float* bo    = (const float*)d_in[10];
    const float* gamma = (const float*)d_in[11];
    const float* beta  = (const float*)d_in[12];
    float* out = (float*)d_out;

    float *pq, *pk, *pv, *pa;
    cudaGetSymbolAddress((void**)&pq, g_q);
    cudaGetSymbolAddress((void**)&pk, g_k);
    cudaGetSymbolAddress((void**)&pv, g_v);
    cudaGetSymbolAddress((void**)&pa, g_attn);

    const int FLASH_SMEM =
        (BR * QSTR + BC * QSTR + BC * VSTR + BR * QSTR + 3 * BR) * 4;
    cudaFuncSetAttribute((const void*)flash_tc,
                         cudaFuncAttributeMaxDynamicSharedMemorySize, FLASH_SMEM);

    dim3 gg(DDIM / BN, MDIM / BM);  // (8, 64)
    sgemm_tc<<<gg, 256>>>(q, Wq, bq, nullptr, pq, MDIM, DDIM, DDIM);
    sgemm_tc<<<gg, 256>>>(k, Wk, bk, nullptr, pk, MDIM, DDIM, DDIM);
    sgemm_tc<<<gg, 256>>>(v, Wv, bv, nullptr, pv, MDIM, DDIM, DDIM);

    flash_tc<<<dim3(SEQ / BR, BATCH * NH), 256, FLASH_SMEM>>>(pq, pk, pv, pa);

    // output projection + bias + residual, into g_k (free now)
    sgemm_tc<<<gg, 256>>>(pa, Wo, bo, q, pk, MDIM, DDIM, DDIM);

    ln_kernel<<<MDIM, 256>>>(pk, gamma, beta, out);
}

// round 3
// speedup vs baseline: 3.1793x; 1.2846x over previous
#include <cuda_runtime.h>
#include <math.h>

#define MDIM 8192      // B*S rows
#define DDIM 1024      // d_model
#define SEQ  2048
#define BATCH 4
#define NH   16
#define DK   64

// Scratch (device globals — no allocation allowed)
__device__ float g_q[(size_t)MDIM * DDIM];
__device__ float g_k[(size_t)MDIM * DDIM];
__device__ float g_v[(size_t)MDIM * DDIM];
__device__ float g_attn[(size_t)MDIM * DDIM];

// ---------------------------------------------------------------------------
// helpers
// ---------------------------------------------------------------------------
__device__ __forceinline__ float to_tf32(float x) {
    unsigned u;
    asm("cvt.rna.tf32.f32 %0, %1;" : "=r"(u) : "f"(x));
    return __uint_as_float(u);
}
__device__ __forceinline__ unsigned fu(float x) { return __float_as_uint(x); }
__device__ __forceinline__ float4 cvt4(float4 v) {
    return make_float4(to_tf32(v.x), to_tf32(v.y), to_tf32(v.z), to_tf32(v.w));
}

__device__ __forceinline__ void mma8(float* c,
                                     unsigned a0, unsigned a1, unsigned a2, unsigned a3,
                                     unsigned b0, unsigned b1) {
    asm volatile(
        "mma.sync.aligned.m16n8k8.row.col.f32.tf32.tf32.f32 "
        "{%0,%1,%2,%3}, {%4,%5,%6,%7}, {%8,%9}, {%0,%1,%2,%3};"
        : "+f"(c[0]), "+f"(c[1]), "+f"(c[2]), "+f"(c[3])
        : "r"(a0), "r"(a1), "r"(a2), "r"(a3), "r"(b0), "r"(b1));
}

// ---------------------------------------------------------------------------
// TF32 tensor-core GEMM: C[m,n] = sum_k A[m,k]*W[n,k] + bias[n] (+ resid)
// A: MxK row-major, W: NxK row-major. 128x128x16 tile, double-buffered smem,
// row-major [row][k] stride-20 layout (conflict-free frag reads, float4 STS).
// ---------------------------------------------------------------------------
#define BM 128
#define BN 128
#define BKT 16
#define ASTR 20   // (qr*20+qc)%32 covers all 32 banks

__global__ __launch_bounds__(256) void sgemm_tc(
    const float* __restrict__ A, const float* __restrict__ W,
    const float* __restrict__ bias, const float* __restrict__ resid,
    float* __restrict__ C, int M, int N, int K)
{
    __shared__ __align__(16) float As[2][BM][ASTR];
    __shared__ __align__(16) float Bs[2][BN][ASTR];

    const int tid  = threadIdx.x;
    const int lane = tid & 31, warp = tid >> 5;
    const int qr = lane >> 2, qc = lane & 3;
    const int wm = (warp >> 1) * 32;   // warp row offset (4)
    const int wn = (warp & 1) * 64;    // warp col offset (2)

    const int lrow = tid >> 2;         // 0..63
    const int lk   = (tid & 3) * 4;    // 0,4,8,12

    const float* Ag = A + (size_t)(blockIdx.y * BM + lrow) * K + lk;
    const float* Wg = W + (size_t)(blockIdx.x * BN + lrow) * K + lk;
    const size_t rstep = (size_t)64 * K;

    float acc[2][8][4];
#pragma unroll
    for (int mi = 0; mi < 2; mi++)
#pragma unroll
        for (int ni = 0; ni < 8; ni++)
#pragma unroll
            for (int j = 0; j < 4; j++) acc[mi][ni][j] = 0.f;

    // prologue: stage 0
    float4 pa0 = *(const float4*)(Ag);
    float4 pa1 = *(const float4*)(Ag + rstep);
    float4 pb0 = *(const float4*)(Wg);
    float4 pb1 = *(const float4*)(Wg + rstep);
    *(float4*)&As[0][lrow][lk]      = cvt4(pa0);
    *(float4*)&As[0][lrow + 64][lk] = cvt4(pa1);
    *(float4*)&Bs[0][lrow][lk]      = cvt4(pb0);
    *(float4*)&Bs[0][lrow + 64][lk] = cvt4(pb1);
    __syncthreads();

    int s = 0;
    for (int k0 = 0; k0 < K; k0 += BKT) {
        const bool pref = (k0 + BKT) < K;
        if (pref) {
            pa0 = *(const float4*)(Ag + k0 + BKT);
            pa1 = *(const float4*)(Ag + rstep + k0 + BKT);
            pb0 = *(const float4*)(Wg + k0 + BKT);
            pb1 = *(const float4*)(Wg + rstep + k0 + BKT);
        }

#pragma unroll
        for (int kk = 0; kk < BKT; kk += 8) {
            unsigned bfr[8][2];
#pragma unroll
            for (int ni = 0; ni < 8; ni++) {
                bfr[ni][0] = fu(Bs[s][wn + ni * 8 + qr][kk + qc]);
                bfr[ni][1] = fu(Bs[s][wn + ni * 8 + qr][kk + qc + 4]);
            }
#pragma unroll
            for (int mi = 0; mi < 2; mi++) {
                const int r0 = wm + mi * 16 + qr;
                unsigned a0 = fu(As[s][r0][kk + qc]);
                unsigned a1 = fu(As[s][r0 + 8][kk + qc]);
                unsigned a2 = fu(As[s][r0][kk + qc + 4]);
                unsigned a3 = fu(As[s][r0 + 8][kk + qc + 4]);
#pragma unroll
                for (int ni = 0; ni < 8; ni++)
                    mma8(acc[mi][ni], a0, a1, a2, a3, bfr[ni][0], bfr[ni][1]);
            }
        }

        if (pref) {
            const int d = s ^ 1;
            *(float4*)&As[d][lrow][lk]      = cvt4(pa0);
            *(float4*)&As[d][lrow + 64][lk] = cvt4(pa1);
            *(float4*)&Bs[d][lrow][lk]      = cvt4(pb0);
            *(float4*)&Bs[d][lrow + 64][lk] = cvt4(pb1);
        }
        __syncthreads();
        s ^= 1;
    }

    // epilogue
#pragma unroll
    for (int mi = 0; mi < 2; mi++) {
        const int row = blockIdx.y * BM + wm + mi * 16 + qr;
#pragma unroll
        for (int ni = 0; ni < 8; ni++) {
            const int col = blockIdx.x * BN + wn + ni * 8 + qc * 2;
            const float b0 = bias[col], b1 = bias[col + 1];
            float x0 = acc[mi][ni][0] + b0, x1 = acc[mi][ni][1] + b1;
            float y0 = acc[mi][ni][2] + b0, y1 = acc[mi][ni][3] + b1;
            if (resid) {
                const float* r0p = resid + (size_t)row * N + col;
                const float* r1p = resid + (size_t)(row + 8) * N + col;
                x0 += r0p[0]; x1 += r0p[1];
                y0 += r1p[0]; y1 += r1p[1];
            }
            float2 v0 = {x0, x1}, v1 = {y0, y1};
            *(float2*)(C + (size_t)row * N + col) = v0;
            *(float2*)(C + (size_t)(row + 8) * N + col) = v1;
        }
    }
}

// ---------------------------------------------------------------------------
// Flash attention, TF32 MMA, register softmax, shfl-based P relayout.
// Grid (SEQ/BR, BATCH*NH), 256 thr = 8 warps; warp tile 16(q) x 64(kv).
// ---------------------------------------------------------------------------
#define BR 128
#define BC 64
#define QP 68   // row-varying frag reads: qr*68+qc -> qr*4+qc mod 32, all banks
#define VP 72   // k-varying  frag reads: qc*72+qr -> qc*8+qr mod 32, all banks

__global__ __launch_bounds__(256) void flash_tc(
    const float* __restrict__ Q, const float* __restrict__ Kg,
    const float* __restrict__ Vg, float* __restrict__ O)
{
    extern __shared__ float sm[];
    float* Qs = sm;                 // BR*QP
    float* Ks = Qs + BR * QP;       // BC*QP
    float* Vs = Ks + BC * QP;       // BC*VP

    const int tid  = threadIdx.x;
    const int lane = tid & 31, warp = tid >> 5;
    const int qr = lane >> 2, qc = lane & 3;
    const int r0 = warp * 16 + qr;      // warp's q rows r0, r0+8

    const int qb = blockIdx.x;
    const int bh = blockIdx.y;
    const int b  = bh >> 4;
    const int h  = bh & 15;
    const size_t base = (size_t)b * SEQ * DDIM + (size_t)h * DK;
    const float qscale = 1.0f / 32.0f;  // 1/sqrt(d_model)

    // Load Q (scaled, tf32)
    {
        const float* Qg = Q + base + (size_t)(qb * BR) * DDIM;
#pragma unroll
        for (int i = 0; i < 8; i++) {
            int t = tid + i * 256;
            int row = t >> 4, c4 = (t & 15) << 2;
            float4 v = *(const float4*)(Qg + (size_t)row * DDIM + c4);
            v.x *= qscale; v.y *= qscale; v.z *= qscale; v.w *= qscale;
            *(float4*)&Qs[row * QP + c4] = cvt4(v);
        }
    }

    float m0 = -1e30f, m1 = -1e30f, l0 = 0.f, l1 = 0.f;
    float oacc[8][4];
#pragma unroll
    for (int ni = 0; ni < 8; ni++)
#pragma unroll
        for (int j = 0; j < 4; j++) oacc[ni][j] = 0.f;

    for (int jt = 0; jt < SEQ / BC; jt++) {
        __syncthreads();   // previous tile's reads done (also covers Q store, it 1)
        const float* Kt = Kg + base + (size_t)(jt * BC) * DDIM;
        const float* Vt = Vg + base + (size_t)(jt * BC) * DDIM;
#pragma unroll
        for (int i = 0; i < 4; i++) {
            int t = tid + i * 256;
            int row = t >> 4, c4 = (t & 15) << 2;
            float4 kv = *(const float4*)(Kt + (size_t)row * DDIM + c4);
            *(float4*)&Ks[row * QP + c4] = cvt4(kv);
            float4 vv = *(const float4*)(Vt + (size_t)row * DDIM + c4);
            *(float4*)&Vs[row * VP + c4] = cvt4(vv);
        }
        __syncthreads();

        // S = Q @ K^T (warp tile 16x64)
        float sacc[8][4];
#pragma unroll
        for (int ni = 0; ni < 8; ni++)
#pragma unroll
            for (int j = 0; j < 4; j++) sacc[ni][j] = 0.f;

#pragma unroll
        for (int k8 = 0; k8 < 8; k8++) {
            const int k = k8 * 8;
            unsigned a0 = fu(Qs[r0 * QP + k + qc]);
            unsigned a1 = fu(Qs[(r0 + 8) * QP + k + qc]);
            unsigned a2 = fu(Qs[r0 * QP + k + qc + 4]);
            unsigned a3 = fu(Qs[(r0 + 8) * QP + k + qc + 4]);
#pragma unroll
            for (int ni = 0; ni < 8; ni++) {
                unsigned b0 = fu(Ks[(ni * 8 + qr) * QP + k + qc]);
                unsigned b1 = fu(Ks[(ni * 8 + qr) * QP + k + qc + 4]);
                mma8(sacc[ni], a0, a1, a2, a3, b0, b1);
            }
        }

        // register softmax (rows qr -> regs 0,1 ; qr+8 -> regs 2,3)
        float mx0 = m0, mx1 = m1;
#pragma unroll
        for (int ni = 0; ni < 8; ni++) {
            mx0 = fmaxf(mx0, fmaxf(sacc[ni][0], sacc[ni][1]));
            mx1 = fmaxf(mx1, fmaxf(sacc[ni][2], sacc[ni][3]));
        }
        mx0 = fmaxf(mx0, __shfl_xor_sync(0xffffffff, mx0, 1));
        mx0 = fmaxf(mx0, __shfl_xor_sync(0xffffffff, mx0, 2));
        mx1 = fmaxf(mx1, __shfl_xor_sync(0xffffffff, mx1, 1));
        mx1 = fmaxf(mx1, __shfl_xor_sync(0xffffffff, mx1, 2));

        const float cf0 = __expf(m0 - mx0);
        const float cf1 = __expf(m1 - mx1);
        m0 = mx0; m1 = mx1;

        float s0 = 0.f, s1 = 0.f;
#pragma unroll
        for (int ni = 0; ni < 8; ni++) {
            float p0 = __expf(sacc[ni][0] - mx0);
            float p1 = __expf(sacc[ni][1] - mx0);
            float p2 = __expf(sacc[ni][2] - mx1);
            float p3 = __expf(sacc[ni][3] - mx1);
            s0 += p0 + p1; s1 += p2 + p3;
            sacc[ni][0] = to_tf32(p0); sacc[ni][1] = to_tf32(p1);
            sacc[ni][2] = to_tf32(p2); sacc[ni][3] = to_tf32(p3);
        }
        s0 += __shfl_xor_sync(0xffffffff, s0, 1);
        s0 += __shfl_xor_sync(0xffffffff, s0, 2);
        s1 += __shfl_xor_sync(0xffffffff, s1, 1);
        s1 += __shfl_xor_sync(0xffffffff, s1, 2);
        l0 = l0 * cf0 + s0;
        l1 = l1 * cf1 + s1;

#pragma unroll
        for (int ni = 0; ni < 8; ni++) {
            oacc[ni][0] *= cf0; oacc[ni][1] *= cf0;
            oacc[ni][2] *= cf1; oacc[ni][3] *= cf1;
        }

        // O += P @ V  : A frag of P built with shfl (C-frag -> A-frag relayout)
        const int src = (lane & ~3) | (qc >> 1);
        const bool odd = (qc & 1);
#pragma unroll
        for (int k8 = 0; k8 < 8; k8++) {
            unsigned c0 = fu(sacc[k8][0]), c1 = fu(sacc[k8][1]);
            unsigned c2 = fu(sacc[k8][2]), c3 = fu(sacc[k8][3]);
            unsigned v00 = __shfl_sync(0xffffffff, c0, src);
            unsigned v01 = __shfl_sync(0xffffffff, c1, src);
            unsigned v20 = __shfl_sync(0xffffffff, c2, src);
            unsigned v21 = __shfl_sync(0xffffffff, c3, src);
            unsigned w00 = __shfl_sync(0xffffffff, c0, src + 2);
            unsigned w01 = __shfl_sync(0xffffffff, c1, src + 2);
            unsigned w20 = __shfl_sync(0xffffffff, c2, src + 2);
            unsigned w21 = __shfl_sync(0xffffffff, c3, src + 2);
            unsigned a0 = odd ? v01 : v00;  // P[qr   ][k8*8+qc  ]
            unsigned a1 = odd ? v21 : v20;  // P[qr+8 ][k8*8+qc  ]
            unsigned a2 = odd ? w01 : w00;  // P[qr   ][k8*8+qc+4]
            unsigned a3 = odd ? w21 : w20;  // P[qr+8 ][k8*8+qc+4]
            const int kv0 = (k8 * 8 + qc) * VP;
            const int kv1 = (k8 * 8 + qc + 4) * VP;
#pragma unroll
            for (int ni = 0; ni < 8; ni++) {
                unsigned b0 = fu(Vs[kv0 + ni * 8 + qr]);
                unsigned b1 = fu(Vs[kv1 + ni * 8 + qr]);
                mma8(oacc[ni], a0, a1, a2, a3, b0, b1);
            }
        }
    }

    // write O / l
    float* Ob = O + base + (size_t)(qb * BR) * DDIM;
    const float inv0 = 1.0f / l0;
    const float inv1 = 1.0f / l1;
#pragma unroll
    for (int ni = 0; ni < 8; ni++) {
        const int col = ni * 8 + qc * 2;
        float2 v0 = {oacc[ni][0] * inv0, oacc[ni][1] * inv0};
        float2 v1 = {oacc[ni][2] * inv1, oacc[ni][3] * inv1};
        *(float2*)(Ob + (size_t)r0 * DDIM + col) = v0;
        *(float2*)(Ob + (size_t)(r0 + 8) * DDIM + col) = v1;
    }
}

// ---------------------------------------------------------------------------
// LayerNorm: one block per row of 1024. 256 threads x 4 elems.
// ---------------------------------------------------------------------------
__global__ __launch_bounds__(256) void ln_kernel(
    const float* __restrict__ X, const float* __restrict__ gamma,
    const float* __restrict__ beta, float* __restrict__ out)
{
    const int row = blockIdx.x;
    const int c = threadIdx.x * 4;
    const float* x = X + (size_t)row * DDIM;

    float4 v = *(const float4*)(x + c);
    float s  = v.x + v.y + v.z + v.w;
    float ss = v.x * v.x + v.y * v.y + v.z * v.z + v.w * v.w;

    __shared__ float reds[32], redss[32];
    for (int off = 16; off > 0; off >>= 1) {
        s  += __shfl_xor_sync(0xffffffff, s, off);
        ss += __shfl_xor_sync(0xffffffff, ss, off);
    }
    const int wid = threadIdx.x >> 5, lid = threadIdx.x & 31;
    if (lid == 0) { reds[wid] = s; redss[wid] = ss; }
    __syncthreads();
    if (wid == 0) {
        float s2  = (lid < 8) ? reds[lid]  : 0.f;
        float ss2 = (lid < 8) ? redss[lid] : 0.f;
        for (int off = 4; off > 0; off >>= 1) {
            s2  += __shfl_xor_sync(0xffffffff, s2, off);
            ss2 += __shfl_xor_sync(0xffffffff, ss2, off);
        }
        if (lid == 0) { reds[0] = s2; redss[0] = ss2; }
    }
    __syncthreads();
    const float mu  = reds[0] * (1.0f / DDIM);
    const float var = redss[0] * (1.0f / DDIM) - mu * mu;
    const float rstd = rsqrtf(var + 1e-5f);

    float4 g  = *(const float4*)(gamma + c);
    float4 be = *(const float4*)(beta + c);
    float4 r;
    r.x = (v.x - mu) * rstd * g.x + be.x;
    r.y = (v.y - mu) * rstd * g.y + be.y;
    r.z = (v.z - mu) * rstd * g.z + be.z;
    r.w = (v.w - mu) * rstd * g.w + be.w;
    *(float4*)(out + (size_t)row * DDIM + c) = r;
}

// ---------------------------------------------------------------------------
extern "C" void kernel_launch(void* const* d_in, const int* in_sizes, int n_in,
                              void* d_out, int out_size)
{
    const float* q     = (const float*)d_in[0];
    const float* k     = (const float*)d_in[1];
    const float* v     = (const float*)d_in[2];
    const float* Wq    = (const float*)d_in[3];
    const float* bq    = (const float*)d_in[4];
    const float* Wk    = (const float*)d_in[5];
    const float* bk    = (const float*)d_in[6];
    const float* Wv    = (const float*)d_in[7];
    const float* bv    = (const float*)d_in[8];
    const float* Wo    = (const float*)d_in[9];
    const float* bo    = (const float*)d_in[10];
    const float* gamma = (const float*)d_in[11];
    const float* beta  = (const float*)d_in[12];
    float* out = (float*)d_out;

    float *pq, *pk, *pv, *pa;
    cudaGetSymbolAddress((void**)&pq, g_q);
    cudaGetSymbolAddress((void**)&pk, g_k);
    cudaGetSymbolAddress((void**)&pv, g_v);
    cudaGetSymbolAddress((void**)&pa, g_attn);

    const int FLASH_SMEM = (BR * QP + BC * QP + BC * VP) * 4;
    cudaFuncSetAttribute((const void*)flash_tc,
                         cudaFuncAttributeMaxDynamicSharedMemorySize, FLASH_SMEM);

    dim3 gg(DDIM / BN, MDIM / BM);  // (8, 64)
    sgemm_tc<<<gg, 256>>>(q, Wq, bq, nullptr, pq, MDIM, DDIM, DDIM);
    sgemm_tc<<<gg, 256>>>(k, Wk, bk, nullptr, pk, MDIM, DDIM, DDIM);
    sgemm_tc<<<gg, 256>>>(v, Wv, bv, nullptr, pv, MDIM, DDIM, DDIM);

    flash_tc<<<dim3(SEQ / BR, BATCH * NH), 256, FLASH_SMEM>>>(pq, pk, pv, pa);

    // output projection + bias + residual, into g_k (free now)
    sgemm_tc<<<gg, 256>>>(pa, Wo, bo, q, pk, MDIM, DDIM, DDIM);

    ln_kernel<<<MDIM, 256>>>(pk, gamma, beta, out);
}